// round 4
// baseline (speedup 1.0000x reference)
#include <cuda_runtime.h>

#define BATCH   8
#define NNODE   256
#define XHIN    9
#define XHHID   64
#define POSHID  192
#define TWO_PI_F 6.283185307179586f
#define NTILE   8      // 256 / 32
#define NPAIR   36     // NTILE*(NTILE+1)/2

// Partial PE sums: [batch][slot][row][freq], freq = [sin 0..63, cos 64..127].
// Row in row-tile T gets j-side partials in slots 0..T-1 (from pairs (ti,T))
// and i-side partials in slots T..7 (from pairs (T,tj)) -> all 8 slots covered
// exactly once => no atomics, no zero-init needed.
__device__ float g_Spart[BATCH][NTILE][NNODE][128];

// ---------------------------------------------------------------------------
// Pair kernel: one block per (batch, upper-triangular 32x32 tile-pair).
// Off-diagonal tiles compute each pair ONCE and contribute to both row sums
// (i-side in registers, j-side via smem staging) -> 0.5625x MUFU vs full.
// grid = 288, block = 256 (8 warps: g = freq-half, r = 8-row group)
// ---------------------------------------------------------------------------
__global__ __launch_bounds__(256) void pair_kernel(
    const float* __restrict__ xh,
    const float* __restrict__ node_mask)
{
    int b = blockIdx.x / NPAIR;
    int p = blockIdx.x % NPAIR;
    int ti = 0, rem = p;
    while (rem >= NTILE - ti) { rem -= NTILE - ti; ti++; }
    int tj = ti + rem;
    bool offdiag = (ti != tj);

    int t = threadIdx.x;
    int w = t >> 5, l = t & 31;
    int r = w & 3;      // row group: i-rows r*8 .. r*8+7 (tile-local)
    int g = w >> 2;     // freq half: freqs g*32 + l

    __shared__ float  xi[3][32], xj[3][32];
    __shared__ float  mi_sm[32], mj_sm[32];
    __shared__ float  a_sm[32 * 32];      // [j][i] : 2*pi*d
    __shared__ float2 SjP[8][16][32];     // [warp][j-in-half][lane] -> 32 KB

    // -- load raw x + masks for both tiles (mean cancels in distances) ------
    if (t < 32) {
        int rowg = b * NNODE + ti * 32 + t;
        xi[0][t] = xh[rowg * XHIN + 0];
        xi[1][t] = xh[rowg * XHIN + 1];
        xi[2][t] = xh[rowg * XHIN + 2];
        mi_sm[t] = node_mask[rowg];
    } else if (t < 64) {
        int tt = t - 32;
        int rowg = b * NNODE + tj * 32 + tt;
        xj[0][tt] = xh[rowg * XHIN + 0];
        xj[1][tt] = xh[rowg * XHIN + 1];
        xj[2][tt] = xh[rowg * XHIN + 2];
        mj_sm[tt] = node_mask[rowg];
    }
    __syncthreads();

    // -- angles a = 2*pi*d for the whole 32x32 tile -------------------------
    #pragma unroll
    for (int k = 0; k < 4; k++) {
        int q = t + k * 256;
        int i = q & 31, j = q >> 5;
        float dx = xi[0][i] - xj[0][j];
        float dy = xi[1][i] - xj[1][j];
        float dz = xi[2][i] - xj[2][j];
        float sq = fmaxf(fmaf(dx, dx, fmaf(dy, dy, dz * dz)), 0.0f);
        a_sm[j * 32 + i] = TWO_PI_F * sqrtf(sq + 1e-12f);
    }
    __syncthreads();

    const float c1 = 0.10381025296522944f;           // log2(100)/64
    float f = exp2f((float)(g * 32 + l) * c1);

    float mi[8];
    #pragma unroll
    for (int k = 0; k < 8; k++) mi[k] = mi_sm[r * 8 + k];

    float ssA[8], ccA[8];
    #pragma unroll
    for (int k = 0; k < 8; k++) { ssA[k] = 0.f; ccA[k] = 0.f; }

    // -- main loop: 2 halves of 16 j each, staged j-side flush --------------
    for (int h = 0; h < 2; h++) {
        #pragma unroll 4
        for (int j2 = 0; j2 < 16; j2++) {
            int j = h * 16 + j2;
            float mj = mj_sm[j];
            const float4* ap = (const float4*)&a_sm[j * 32 + r * 8];
            float4 a0 = ap[0];
            float4 a1 = ap[1];
            float av[8] = {a0.x, a0.y, a0.z, a0.w, a1.x, a1.y, a1.z, a1.w};
            float sjs = 0.f, sjc = 0.f;
            #pragma unroll
            for (int k = 0; k < 8; k++) {
                float ang = av[k] * f;
                float s = __sinf(ang);
                float c = __cosf(ang);
                ssA[k] = fmaf(mj, s, ssA[k]);       // i-side: += m_j * sin
                ccA[k] = fmaf(mj, c, ccA[k]);
                sjs    = fmaf(mi[k], s, sjs);       // j-side: += m_i * sin
                sjc    = fmaf(mi[k], c, sjc);
            }
            if (offdiag) SjP[w][j2][l] = make_float2(sjs, sjc);
        }

        if (offdiag) {
            __syncthreads();
            // reduce 4 row-group warps per freq-half, write j-side partials
            #pragma unroll
            for (int k = 0; k < 4; k++) {
                int idx = t + k * 256;               // 0..1023
                int gg  = idx >> 9;                  // freq half
                int jj  = (idx >> 5) & 15;           // j within half
                int ll  = idx & 31;                  // lane/freq
                float2 v0 = SjP[gg * 4 + 0][jj][ll];
                float2 v1 = SjP[gg * 4 + 1][jj][ll];
                float2 v2 = SjP[gg * 4 + 2][jj][ll];
                float2 v3 = SjP[gg * 4 + 3][jj][ll];
                float ss = (v0.x + v1.x) + (v2.x + v3.x);
                float cc = (v0.y + v1.y) + (v2.y + v3.y);
                float* rp = &g_Spart[b][ti][tj * 32 + h * 16 + jj][0];
                rp[gg * 32 + ll]      = ss;
                rp[64 + gg * 32 + ll] = cc;
            }
            __syncthreads();
        }
    }

    // -- i-side flush -------------------------------------------------------
    float* basei = &g_Spart[b][tj][ti * 32][0];
    #pragma unroll
    for (int k = 0; k < 8; k++) {
        float* rp = basei + (r * 8 + k) * 128;
        rp[g * 32 + l]      = ssA[k];
        rp[64 + g * 32 + l] = ccA[k];
    }
}

// ---------------------------------------------------------------------------
// Epilogue: per (batch, 8 rows): sum the 8 slot partials, fold mask_i/N,
// project 128->192 with W_pos (one W_pos pass serves 8 rows -> 4x less L2
// traffic than 2-rows/block, 8-way FMA ILP per load), plus the 9->64 xh
// embedding (masked mean recomputed per block with a shuffle reduction).
// grid = 256, block = 256
// ---------------------------------------------------------------------------
__global__ __launch_bounds__(256) void ep_ditemb(
    const float* __restrict__ xh,
    const float* __restrict__ node_mask,
    const float* __restrict__ W_xh,
    const float* __restrict__ b_xh,
    const float* __restrict__ W_pos,
    const float* __restrict__ b_pos,
    float* __restrict__ out)
{
    int b  = blockIdx.x >> 5;           // 32 blocks per batch
    int i0 = (blockIdx.x & 31) << 3;    // 8 rows per block
    int t  = threadIdx.x;
    int w  = t >> 5, l = t & 31;

    __shared__ float  mk[NNODE];
    __shared__ float4 S4[128][2];       // S layout [k][row] as 2x float4
    __shared__ float  wred[8][4];
    __shared__ float  mean_s[3];
    __shared__ float  sc[2];            // [0]=1/N, [1]=256/N
    __shared__ float  xc8[8][3];        // centered x for the 8 rows
    __shared__ float  hs[8][6];         // h features for the 8 rows
    __shared__ float  sW[XHIN * XHHID];
    __shared__ float  sB[XHHID];

    // -- slot-sum loads issued first (32 independent coalesced LDG) ---------
    float ssum[4];
    #pragma unroll
    for (int k = 0; k < 4; k++) {
        int v = t + k * 256;
        int rv = v >> 7, fv = v & 127;
        float s = 0.f;
        #pragma unroll
        for (int slot = 0; slot < NTILE; slot++)
            s += g_Spart[b][slot][i0 + rv][fv];
        ssum[k] = s;
    }

    // -- masked mean / N reduction (overlaps the L2 latency above) ----------
    int row = b * NNODE + t;
    float m  = node_mask[row];
    float x0 = xh[row * XHIN + 0];
    float x1 = xh[row * XHIN + 1];
    float x2 = xh[row * XHIN + 2];
    mk[t] = m;

    float p0 = x0 * m, p1 = x1 * m, p2 = x2 * m, p3 = m;
    #pragma unroll
    for (int off = 16; off > 0; off >>= 1) {
        p0 += __shfl_down_sync(0xffffffffu, p0, off);
        p1 += __shfl_down_sync(0xffffffffu, p1, off);
        p2 += __shfl_down_sync(0xffffffffu, p2, off);
        p3 += __shfl_down_sync(0xffffffffu, p3, off);
    }
    if (l == 0) { wred[w][0] = p0; wred[w][1] = p1; wred[w][2] = p2; wred[w][3] = p3; }

    // stage embedding weights + h rows
    for (int i = t; i < XHIN * XHHID; i += 256) sW[i] = W_xh[i];
    if (t < XHHID) sB[t] = b_xh[t];
    if (t < 48) {
        int rr = t / 6, cc = t % 6;
        hs[rr][cc] = xh[(size_t)(b * NNODE + i0 + rr) * XHIN + 3 + cc];
    }
    __syncthreads();

    if (t < 4) {
        float s = wred[0][t] + wred[1][t] + wred[2][t] + wred[3][t]
                + wred[4][t] + wred[5][t] + wred[6][t] + wred[7][t];
        wred[0][t] = s;
    }
    __syncthreads();
    if (t < 3) mean_s[t] = wred[0][t] / wred[0][3];
    if (t == 0) {
        float Ns = wred[0][3];
        sc[0] = 1.0f / Ns;
        sc[1] = 256.0f / Ns;
    }
    __syncthreads();

    // centered x for the block's 8 rows (reference arithmetic)
    if (t >= i0 && t < i0 + 8) {
        int k = t - i0;
        xc8[k][0] = (x0 - mean_s[0]) * m;
        xc8[k][1] = (x1 - mean_s[1]) * m;
        xc8[k][2] = (x2 - mean_s[2]) * m;
    }

    // finalize S = (slot sum) * mask_i / N, stored [k][row]
    {
        float* Ssc = (float*)S4;
        #pragma unroll
        for (int k = 0; k < 4; k++) {
            int v = t + k * 256;
            int rv = v >> 7, fv = v & 127;
            Ssc[fv * 8 + rv] = ssum[k] * mk[i0 + rv] * sc[0];
        }
    }
    __syncthreads();

    // -- PE projection: S(8x128) @ W_pos(128x192) + bias --------------------
    if (t < POSHID) {
        float acc[8];
        #pragma unroll
        for (int r = 0; r < 8; r++) acc[r] = 0.f;
        #pragma unroll 4
        for (int k = 0; k < 128; k++) {
            float4 lo = S4[k][0];
            float4 hi = S4[k][1];
            float wv = W_pos[k * POSHID + t];
            acc[0] = fmaf(lo.x, wv, acc[0]);
            acc[1] = fmaf(lo.y, wv, acc[1]);
            acc[2] = fmaf(lo.z, wv, acc[2]);
            acc[3] = fmaf(lo.w, wv, acc[3]);
            acc[4] = fmaf(hi.x, wv, acc[4]);
            acc[5] = fmaf(hi.y, wv, acc[5]);
            acc[6] = fmaf(hi.z, wv, acc[6]);
            acc[7] = fmaf(hi.w, wv, acc[7]);
        }
        float bp = b_pos[t] * sc[1];
        size_t base = ((size_t)(b * NNODE + i0)) * 256 + 64;
        #pragma unroll
        for (int r = 0; r < 8; r++)
            out[base + (size_t)r * 256 + t] = (acc[r] + bp) * mk[i0 + r];
    }

    // -- xh embedding for the 8 rows (512 outputs, 2 per thread) ------------
    #pragma unroll
    for (int e = 0; e < 2; e++) {
        int v = t + e * 256;
        int r = v >> 6, o = v & 63;
        float mr = mk[i0 + r];
        float acc = sB[o];
        acc = fmaf(xc8[r][0], sW[0 * XHHID + o], acc);
        acc = fmaf(xc8[r][1], sW[1 * XHHID + o], acc);
        acc = fmaf(xc8[r][2], sW[2 * XHHID + o], acc);
        acc = fmaf(hs[r][0],  sW[3 * XHHID + o], acc);
        acc = fmaf(hs[r][1],  sW[4 * XHHID + o], acc);
        acc = fmaf(hs[r][2],  sW[5 * XHHID + o], acc);
        acc = fmaf(hs[r][3],  sW[6 * XHHID + o], acc);
        acc = fmaf(hs[r][4],  sW[7 * XHHID + o], acc);
        acc = fmaf(hs[r][5],  sW[8 * XHHID + o], acc);
        out[(size_t)(b * NNODE + i0 + r) * 256 + o] = acc * mr;
    }
}

extern "C" void kernel_launch(void* const* d_in, const int* in_sizes, int n_in,
                              void* d_out, int out_size)
{
    // inputs (metadata order): t, xh, node_mask, edge_mask, W_xh, b_xh, W_pos, b_pos
    const float* xh        = (const float*)d_in[1];
    const float* node_mask = (const float*)d_in[2];
    const float* W_xh      = (const float*)d_in[4];
    const float* b_xh      = (const float*)d_in[5];
    const float* W_pos     = (const float*)d_in[6];
    const float* b_pos     = (const float*)d_in[7];
    float* out = (float*)d_out;

    pair_kernel<<<BATCH * NPAIR, 256>>>(xh, node_mask);
    ep_ditemb<<<BATCH * (NNODE / 8), 256>>>(xh, node_mask, W_xh, b_xh,
                                            W_pos, b_pos, out);
}

// round 6
// speedup vs baseline: 1.0839x; 1.0839x over previous
#include <cuda_runtime.h>

#define BATCH   8
#define NNODE   256
#define XHIN    9
#define XHHID   64
#define POSHID  192
#define TWO_PI_F 6.283185307179586f
#define NTILE   8      // 256 / 32
#define NPAIR   36     // NTILE*(NTILE+1)/2
#define WPOS_FLOATS (128 * POSHID)          // 24576
#define WPOS_BYTES  (WPOS_FLOATS * 4)       // 98304

// Partial PE sums: [batch][slot][row][freq], freq = [sin 0..63, cos 64..127].
// Row in row-tile T gets j-side partials in slots 0..T-1 (from pairs (ti,T))
// and i-side partials in slots T..7 (from pairs (T,tj)) -> all 8 slots covered
// exactly once => no atomics, no zero-init needed.
__device__ float g_Spart[BATCH][NTILE][NNODE][128];

// ---------------------------------------------------------------------------
// Pair kernel (unchanged, at its MUFU floor): one block per (batch, upper-tri
// 32x32 tile-pair). Off-diagonal tiles computed ONCE, contribute both sides.
// grid = 288, block = 256
// ---------------------------------------------------------------------------
__global__ __launch_bounds__(256) void pair_kernel(
    const float* __restrict__ xh,
    const float* __restrict__ node_mask)
{
    int b = blockIdx.x / NPAIR;
    int p = blockIdx.x % NPAIR;
    int ti = 0, rem = p;
    while (rem >= NTILE - ti) { rem -= NTILE - ti; ti++; }
    int tj = ti + rem;
    bool offdiag = (ti != tj);

    int t = threadIdx.x;
    int w = t >> 5, l = t & 31;
    int r = w & 3;
    int g = w >> 2;

    __shared__ float  xi[3][32], xj[3][32];
    __shared__ float  mi_sm[32], mj_sm[32];
    __shared__ float  a_sm[32 * 32];
    __shared__ float2 SjP[8][16][32];

    if (t < 32) {
        int rowg = b * NNODE + ti * 32 + t;
        xi[0][t] = xh[rowg * XHIN + 0];
        xi[1][t] = xh[rowg * XHIN + 1];
        xi[2][t] = xh[rowg * XHIN + 2];
        mi_sm[t] = node_mask[rowg];
    } else if (t < 64) {
        int tt = t - 32;
        int rowg = b * NNODE + tj * 32 + tt;
        xj[0][tt] = xh[rowg * XHIN + 0];
        xj[1][tt] = xh[rowg * XHIN + 1];
        xj[2][tt] = xh[rowg * XHIN + 2];
        mj_sm[tt] = node_mask[rowg];
    }
    __syncthreads();

    #pragma unroll
    for (int k = 0; k < 4; k++) {
        int q = t + k * 256;
        int i = q & 31, j = q >> 5;
        float dx = xi[0][i] - xj[0][j];
        float dy = xi[1][i] - xj[1][j];
        float dz = xi[2][i] - xj[2][j];
        float sq = fmaxf(fmaf(dx, dx, fmaf(dy, dy, dz * dz)), 0.0f);
        a_sm[j * 32 + i] = TWO_PI_F * sqrtf(sq + 1e-12f);
    }
    __syncthreads();

    const float c1 = 0.10381025296522944f;           // log2(100)/64
    float f = exp2f((float)(g * 32 + l) * c1);

    float mi[8];
    #pragma unroll
    for (int k = 0; k < 8; k++) mi[k] = mi_sm[r * 8 + k];

    float ssA[8], ccA[8];
    #pragma unroll
    for (int k = 0; k < 8; k++) { ssA[k] = 0.f; ccA[k] = 0.f; }

    for (int h = 0; h < 2; h++) {
        #pragma unroll 4
        for (int j2 = 0; j2 < 16; j2++) {
            int j = h * 16 + j2;
            float mj = mj_sm[j];
            const float4* ap = (const float4*)&a_sm[j * 32 + r * 8];
            float4 a0 = ap[0];
            float4 a1 = ap[1];
            float av[8] = {a0.x, a0.y, a0.z, a0.w, a1.x, a1.y, a1.z, a1.w};
            float sjs = 0.f, sjc = 0.f;
            #pragma unroll
            for (int k = 0; k < 8; k++) {
                float ang = av[k] * f;
                float s = __sinf(ang);
                float c = __cosf(ang);
                ssA[k] = fmaf(mj, s, ssA[k]);
                ccA[k] = fmaf(mj, c, ccA[k]);
                sjs    = fmaf(mi[k], s, sjs);
                sjc    = fmaf(mi[k], c, sjc);
            }
            if (offdiag) SjP[w][j2][l] = make_float2(sjs, sjc);
        }

        if (offdiag) {
            __syncthreads();
            #pragma unroll
            for (int k = 0; k < 4; k++) {
                int idx = t + k * 256;
                int gg  = idx >> 9;
                int jj  = (idx >> 5) & 15;
                int ll  = idx & 31;
                float2 v0 = SjP[gg * 4 + 0][jj][ll];
                float2 v1 = SjP[gg * 4 + 1][jj][ll];
                float2 v2 = SjP[gg * 4 + 2][jj][ll];
                float2 v3 = SjP[gg * 4 + 3][jj][ll];
                float ss = (v0.x + v1.x) + (v2.x + v3.x);
                float cc = (v0.y + v1.y) + (v2.y + v3.y);
                float* rp = &g_Spart[b][ti][tj * 32 + h * 16 + jj][0];
                rp[gg * 32 + ll]      = ss;
                rp[64 + gg * 32 + ll] = cc;
            }
            __syncthreads();
        }
    }

    float* basei = &g_Spart[b][tj][ti * 32][0];
    #pragma unroll
    for (int k = 0; k < 8; k++) {
        float* rp = basei + (r * 8 + k) * 128;
        rp[g * 32 + l]      = ssA[k];
        rp[64 + g * 32 + l] = ccA[k];
    }
}

// ---------------------------------------------------------------------------
// Epilogue v3: 256 blocks x 8 rows, W_pos fully staged in 96KB dynamic smem
// (bulk high-MLP copy decoupled from the matvec), matvec = pure LDS+FMA with
// 8-row ILP on warps 0-5 while warps 6-7 do the 9->64 xh embedding.
// 2 blocks/SM -> all 256 blocks resident in one wave.
// grid = 256, block = 256, dynamic smem = 98304 B
// ---------------------------------------------------------------------------
__global__ __launch_bounds__(256, 2) void ep_ditemb(
    const float* __restrict__ xh,
    const float* __restrict__ node_mask,
    const float* __restrict__ W_xh,
    const float* __restrict__ b_xh,
    const float* __restrict__ W_pos,
    const float* __restrict__ b_pos,
    float* __restrict__ out)
{
    extern __shared__ float sWpos[];     // 24576 floats = full W_pos

    int b  = blockIdx.x >> 5;            // 32 blocks per batch
    int i0 = (blockIdx.x & 31) << 3;     // 8 rows per block
    int t  = threadIdx.x;
    int w  = t >> 5, l = t & 31;

    __shared__ float  mk[NNODE];
    __shared__ float4 S4[128][2];        // S layout [k][row] as 2x float4
    __shared__ float  wred[8][4];
    __shared__ float  mean_s[3];
    __shared__ float  sc[2];             // [0]=1/N, [1]=256/N
    __shared__ float  xc8[8][3];
    __shared__ float  hs[8][6];
    __shared__ float  sW[XHIN * XHHID];
    __shared__ float  sB[XHHID];

    // -- bulk W_pos stage: 24 independent LDG.128 per thread -----------------
    {
        float4*       dst = (float4*)sWpos;
        const float4* src = (const float4*)W_pos;
        #pragma unroll 6
        for (int i = t; i < WPOS_FLOATS / 4; i += 256) dst[i] = src[i];
    }

    // -- slot-sum loads (32 independent coalesced LDG) -----------------------
    float ssum[4];
    #pragma unroll
    for (int k = 0; k < 4; k++) {
        int v = t + k * 256;
        int rv = v >> 7, fv = v & 127;
        float s = 0.f;
        #pragma unroll
        for (int slot = 0; slot < NTILE; slot++)
            s += g_Spart[b][slot][i0 + rv][fv];
        ssum[k] = s;
    }

    // -- masked mean / N reduction (overlaps the loads above) ----------------
    int row = b * NNODE + t;
    float m  = node_mask[row];
    float x0 = xh[row * XHIN + 0];
    float x1 = xh[row * XHIN + 1];
    float x2 = xh[row * XHIN + 2];
    mk[t] = m;

    float p0 = x0 * m, p1 = x1 * m, p2 = x2 * m, p3 = m;
    #pragma unroll
    for (int off = 16; off > 0; off >>= 1) {
        p0 += __shfl_down_sync(0xffffffffu, p0, off);
        p1 += __shfl_down_sync(0xffffffffu, p1, off);
        p2 += __shfl_down_sync(0xffffffffu, p2, off);
        p3 += __shfl_down_sync(0xffffffffu, p3, off);
    }
    if (l == 0) { wred[w][0] = p0; wred[w][1] = p1; wred[w][2] = p2; wred[w][3] = p3; }

    for (int i = t; i < XHIN * XHHID; i += 256) sW[i] = W_xh[i];
    if (t < XHHID) sB[t] = b_xh[t];
    if (t < 48) {
        int rr = t / 6, cc = t % 6;
        hs[rr][cc] = xh[(size_t)(b * NNODE + i0 + rr) * XHIN + 3 + cc];
    }
    __syncthreads();

    if (t < 4) {
        float s = wred[0][t] + wred[1][t] + wred[2][t] + wred[3][t]
                + wred[4][t] + wred[5][t] + wred[6][t] + wred[7][t];
        wred[0][t] = s;
    }
    __syncthreads();
    if (t < 3) mean_s[t] = wred[0][t] / wred[0][3];
    if (t == 0) {
        float Ns = wred[0][3];
        sc[0] = 1.0f / Ns;
        sc[1] = 256.0f / Ns;
    }
    __syncthreads();

    if (t >= i0 && t < i0 + 8) {
        int k = t - i0;
        xc8[k][0] = (x0 - mean_s[0]) * m;
        xc8[k][1] = (x1 - mean_s[1]) * m;
        xc8[k][2] = (x2 - mean_s[2]) * m;
    }

    {
        float* Ssc = (float*)S4;
        #pragma unroll
        for (int k = 0; k < 4; k++) {
            int v = t + k * 256;
            int rv = v >> 7, fv = v & 127;
            Ssc[fv * 8 + rv] = ssum[k] * mk[i0 + rv] * sc[0];
        }
    }
    __syncthreads();

    if (t < POSHID) {
        // -- PE projection from smem: S(8x128) @ W_pos(128x192) + bias ------
        float acc[8];
        #pragma unroll
        for (int r = 0; r < 8; r++) acc[r] = 0.f;
        #pragma unroll 8
        for (int k = 0; k < 128; k++) {
            float4 lo = S4[k][0];
            float4 hi = S4[k][1];
            float wv = sWpos[k * POSHID + t];
            acc[0] = fmaf(lo.x, wv, acc[0]);
            acc[1] = fmaf(lo.y, wv, acc[1]);
            acc[2] = fmaf(lo.z, wv, acc[2]);
            acc[3] = fmaf(lo.w, wv, acc[3]);
            acc[4] = fmaf(hi.x, wv, acc[4]);
            acc[5] = fmaf(hi.y, wv, acc[5]);
            acc[6] = fmaf(hi.z, wv, acc[6]);
            acc[7] = fmaf(hi.w, wv, acc[7]);
        }
        float bp = b_pos[t] * sc[1];
        size_t base = ((size_t)(b * NNODE + i0)) * 256 + 64;
        #pragma unroll
        for (int r = 0; r < 8; r++)
            out[base + (size_t)r * 256 + t] = (acc[r] + bp) * mk[i0 + r];
    } else {
        // -- xh embedding: 64 threads x 8 outputs ---------------------------
        int tt = t - POSHID;
        #pragma unroll
        for (int e = 0; e < 8; e++) {
            int v = tt * 8 + e;                  // 0..511
            int r = v >> 6, o = v & 63;
            float mr = mk[i0 + r];
            float acc = sB[o];
            acc = fmaf(xc8[r][0], sW[0 * XHHID + o], acc);
            acc = fmaf(xc8[r][1], sW[1 * XHHID + o], acc);
            acc = fmaf(xc8[r][2], sW[2 * XHHID + o], acc);
            acc = fmaf(hs[r][0],  sW[3 * XHHID + o], acc);
            acc = fmaf(hs[r][1],  sW[4 * XHHID + o], acc);
            acc = fmaf(hs[r][2],  sW[5 * XHHID + o], acc);
            acc = fmaf(hs[r][3],  sW[6 * XHHID + o], acc);
            acc = fmaf(hs[r][4],  sW[7 * XHHID + o], acc);
            acc = fmaf(hs[r][5],  sW[8 * XHHID + o], acc);
            out[(size_t)(b * NNODE + i0 + r) * 256 + o] = acc * mr;
        }
    }
}

extern "C" void kernel_launch(void* const* d_in, const int* in_sizes, int n_in,
                              void* d_out, int out_size)
{
    // inputs (metadata order): t, xh, node_mask, edge_mask, W_xh, b_xh, W_pos, b_pos
    const float* xh        = (const float*)d_in[1];
    const float* node_mask = (const float*)d_in[2];
    const float* W_xh      = (const float*)d_in[4];
    const float* b_xh      = (const float*)d_in[5];
    const float* W_pos     = (const float*)d_in[6];
    const float* b_pos     = (const float*)d_in[7];
    float* out = (float*)d_out;

    cudaFuncSetAttribute(ep_ditemb,
                         cudaFuncAttributeMaxDynamicSharedMemorySize,
                         WPOS_BYTES);

    pair_kernel<<<BATCH * NPAIR, 256>>>(xh, node_mask);
    ep_ditemb<<<BATCH * (NNODE / 8), 256, WPOS_BYTES>>>(
        xh, node_mask, W_xh, b_xh, W_pos, b_pos, out);
}